// round 10
// baseline (speedup 1.0000x reference)
#include <cuda_runtime.h>

// Problem constants (fixed: B=16, N=8192, C=256, num_points=2048)
#define BB   16
#define NN   8192
#define CC   256
#define MM   2048
#define TT   1024          // threads per FPS block
#define PPT  (NN / TT)     // points per thread = 8
#define NPAIR (PPT / 2)    // f32x2 pairs per thread = 4

// Scratch: selected indices, written by FPS kernel, read by gather kernel.
__device__ int g_idx[BB * MM];

// Dynamic smem: sq4[NN] float4 | pvi[64] uint2 | initv[32] | initi[32] |
//               cent[96] | skx[NN] float | ski[NN] int
#define SMEM_BYTES (NN * 16 + 64 * 8 + 32 * 4 + 32 * 4 + 96 * 4 + NN * 4 + NN * 4)

// ---- packed f32x2 helpers (sm_103a) ---------------------------------------
__device__ __forceinline__ unsigned long long pack2(float lo, float hi) {
    unsigned long long r;
    asm("mov.b64 %0, {%1, %2};" : "=l"(r) : "f"(lo), "f"(hi));
    return r;
}
__device__ __forceinline__ void unpack2(unsigned long long v, float& lo, float& hi) {
    asm("mov.b64 {%0, %1}, %2;" : "=f"(lo), "=f"(hi) : "l"(v));
}
__device__ __forceinline__ unsigned long long add2(unsigned long long a, unsigned long long b) {
    unsigned long long r;
    asm("add.rn.f32x2 %0, %1, %2;" : "=l"(r) : "l"(a), "l"(b));
    return r;
}
__device__ __forceinline__ unsigned long long mul2(unsigned long long a, unsigned long long b) {
    unsigned long long r;
    asm("mul.rn.f32x2 %0, %1, %2;" : "=l"(r) : "l"(a), "l"(b));
    return r;
}
// ---------------------------------------------------------------------------

__device__ __forceinline__ float warp_sum(float x) {
    #pragma unroll
    for (int o = 16; o > 0; o >>= 1)
        x += __shfl_xor_sync(0xFFFFFFFFu, x, o);
    return x;
}
__device__ __forceinline__ float warp_min(float x) {
    #pragma unroll
    for (int o = 16; o > 0; o >>= 1)
        x = fminf(x, __shfl_xor_sync(0xFFFFFFFFu, x, o));
    return x;
}
__device__ __forceinline__ float warp_max(float x) {
    #pragma unroll
    for (int o = 16; o > 0; o >>= 1)
        x = fmaxf(x, __shfl_xor_sync(0xFFFFFFFFu, x, o));
    return x;
}

extern "C" __global__ void __launch_bounds__(TT, 1)
fps_kernel(const float* __restrict__ pts,   // [B, 3, N]
           float* __restrict__ out_pts)     // [B, M, 3]
{
    extern __shared__ unsigned char smraw[];
    float4*   sq4   = (float4*)smraw;                  // [NN] orig-indexed coords
    uint2*    pvi   = (uint2*)(smraw + NN * 16);       // [64] (val,cand), 2 bufs
    unsigned* initv = (unsigned*)(pvi + 64);           // [32]
    unsigned* initi = initv + 32;                      // [32]
    float*    cent  = (float*)(initi + 32);            // [96]
    float*    skx   = cent + 96;                       // [NN] sort keys (x)
    int*      ski   = (int*)(skx + NN);                // [NN] orig indices

    const int b    = blockIdx.x;
    const int tid  = threadIdx.x;
    const int lane = tid & 31;
    const int warp = tid >> 5;

    const float* px = pts + (size_t)b * 3 * NN;
    const float* py = px + NN;
    const float* pz = px + 2 * NN;

    // ---- load (orig layout), centroid sums, sort-key init ----
    float s1 = 0.f, s2 = 0.f, s3 = 0.f;
    #pragma unroll
    for (int k = 0; k < PPT; k++) {
        int n = tid + k * TT;               // coalesced
        float x = px[n], y = py[n], z = pz[n];
        sq4[n] = make_float4(x, y, z, 0.f);
        skx[n] = x; ski[n] = n;
        s1 += x; s2 += y; s3 += z;
    }

    // Deterministic centroid (exact, one-shot).
    s1 = warp_sum(s1); s2 = warp_sum(s2); s3 = warp_sum(s3);
    if (lane == 0) { cent[warp] = s1; cent[32 + warp] = s2; cent[64 + warp] = s3; }

    // ---- bitonic sort by x (permutation-preserving; quality only affects
    //      pruning, never correctness) ----
    for (int k = 2; k <= NN; k <<= 1) {
        for (int j = k >> 1; j > 0; j >>= 1) {
            __syncthreads();
            #pragma unroll 4
            for (int t = tid; t < NN / 2; t += TT) {
                int i = 2 * t - (t & (j - 1));
                int l = i + j;
                bool up = ((i & k) == 0);
                float a = skx[i], c = skx[l];
                bool sw = up ? (a > c) : (a < c);
                if (sw) {
                    skx[i] = c; skx[l] = a;
                    int ta = ski[i]; ski[i] = ski[l]; ski[l] = ta;
                }
            }
        }
    }
    __syncthreads();

    // ---- reorder into registers: warp w owns sorted ranks [256w, 256w+256).
    //      Group A = ranks [256w,256w+128) (k=0..3), group B = the rest. ----
    unsigned long long X2[NPAIR], Y2[NPAIR], Z2[NPAIR];
    unsigned OI2[NPAIR];                    // packed orig indices (lo | hi<<16)
    float dr[PPT];
    float xs[PPT], ys[PPT], zs[PPT];
    unsigned oi[PPT];
    const int base = warp * 256 + lane;
    #pragma unroll
    for (int k = 0; k < PPT; k++) {
        int r = base + 32 * k;
        int idx = ski[r];
        float4 p = sq4[idx];
        xs[k] = p.x; ys[k] = p.y; zs[k] = p.z;
        oi[k] = (unsigned)idx;
        dr[k] = 1e10f;
    }
    #pragma unroll
    for (int j = 0; j < NPAIR; j++) {
        X2[j] = pack2(xs[2 * j], xs[2 * j + 1]);
        Y2[j] = pack2(ys[2 * j], ys[2 * j + 1]);
        Z2[j] = pack2(zs[2 * j], zs[2 * j + 1]);
        OI2[j] = oi[2 * j] | (oi[2 * j + 1] << 16);
    }
    // Group x-extents (from the points actually held -> always safe).
    float xmnA = fminf(fminf(xs[0], xs[1]), fminf(xs[2], xs[3]));
    float xmxA = fmaxf(fmaxf(xs[0], xs[1]), fmaxf(xs[2], xs[3]));
    float xmnB = fminf(fminf(xs[4], xs[5]), fminf(xs[6], xs[7]));
    float xmxB = fmaxf(fmaxf(xs[4], xs[5]), fmaxf(xs[6], xs[7]));
    xmnA = warp_min(xmnA); xmxA = warp_max(xmxA);
    xmnB = warp_min(xmnB); xmxB = warp_max(xmxB);

    // Centroid finalize.
    float cx = warp_sum(cent[lane])      * (1.0f / NN);
    float cy = warp_sum(cent[32 + lane]) * (1.0f / NN);
    float cz = warp_sum(cent[64 + lane]) * (1.0f / NN);

    // d0 = ||p - centroid||^2, initial farthest (exact plain form; orig-idx
    // tie-break since held points are no longer index-ordered).
    float best = -1.0f; unsigned bi = 0xFFFFFFFFu;
    #pragma unroll
    for (int k = 0; k < PPT; k++) {
        float dx = xs[k] - cx, dy = ys[k] - cy, dz = zs[k] - cz;
        float d = __fadd_rn(__fadd_rn(__fmul_rn(dx, dx), __fmul_rn(dy, dy)),
                            __fmul_rn(dz, dz));
        if (d > best)            { best = d; bi = oi[k]; }
        else if (d == best && oi[k] < bi) bi = oi[k];
    }
    {
        unsigned vb = __float_as_uint(best);
        unsigned m1 = __reduce_max_sync(0xFFFFFFFFu, vb);
        unsigned c1 = (vb == m1) ? bi : 0xFFFFFFFFu;
        unsigned i1 = __reduce_min_sync(0xFFFFFFFFu, c1);
        if (lane == 0) { initv[warp] = m1; initi[warp] = i1; }
    }
    __syncthreads();
    unsigned far;
    {
        unsigned v2 = initv[lane];
        unsigned i2 = initi[lane];
        unsigned m2 = __reduce_max_sync(0xFFFFFFFFu, v2);
        unsigned c2 = (v2 == m2) ? i2 : 0xFFFFFFFFu;
        far = __reduce_min_sync(0xFFFFFFFFu, c2);
    }

    float* outp = out_pts + (size_t)b * MM * 3;
    int*   idxp = g_idx + b * MM;

    // Per-group cached state (exact while skipped): max-dr bits, min orig idx
    // among bit-equal ties, and the precomputed active interval [xlo, xhi].
    unsigned gvbA = __float_as_uint(1e10f), gvbB = __float_as_uint(1e10f);
    unsigned gcA  = 0xFFFFFFFFu,            gcB  = 0xFFFFFFFFu;
    float xloA = -1e30f, xhiA = 1e30f;      // always active first iteration
    float xloB = -1e30f, xhiB = 1e30f;

    for (int m = 0; m < MM; m++) {
        const int buf = m & 1;
        // Broadcast the selected point (one LDS.128, orig-indexed table).
        float4 q = sq4[far];
        if (tid == 0) {
            idxp[m] = (int)far;
            outp[m * 3 + 0] = q.x;
            outp[m * 3 + 1] = q.y;
            outp[m * 3 + 2] = q.z;
        }

        // Interval prune: q.x outside [xlo, xhi] with xlo = xmn - rw,
        // xhi = xmx + rw, rw = sqrt(gmax)*1.0001 ==> every fminf in the group
        // is a bit-level no-op (dx^2 alone already exceeds gmax by >1e-4 rel,
        // dwarfing all <= ~6 ulp rounding). Caches stay exact.
        bool aA = (q.x >= xloA) && (q.x <= xhiA);
        bool aB = (q.x >= xloB) && (q.x <= xhiB);

        if (aA | aB) {
            unsigned long long nqx2 = pack2(-q.x, -q.x);
            unsigned long long nqy2 = pack2(-q.y, -q.y);
            unsigned long long nqz2 = pack2(-q.z, -q.z);
            if (aA) {
                #pragma unroll
                for (int j = 0; j < 2; j++) {
                    unsigned long long dx2 = add2(X2[j], nqx2);
                    unsigned long long dy2 = add2(Y2[j], nqy2);
                    unsigned long long dz2 = add2(Z2[j], nqz2);
                    unsigned long long d2 = add2(add2(mul2(dx2, dx2), mul2(dy2, dy2)),
                                                 mul2(dz2, dz2));
                    float dlo, dhi;
                    unpack2(d2, dlo, dhi);
                    dr[2 * j]     = fminf(dr[2 * j],     dlo);
                    dr[2 * j + 1] = fminf(dr[2 * j + 1], dhi);
                }
                float mxg = fmaxf(fmaxf(dr[0], dr[1]), fmaxf(dr[2], dr[3]));
                gvbA = __reduce_max_sync(0xFFFFFFFFu, __float_as_uint(mxg));
                unsigned cand = 0xFFFFFFFFu;
                if (__float_as_uint(dr[0]) == gvbA) cand = OI2[0] & 0xFFFFu;
                if (__float_as_uint(dr[1]) == gvbA) cand = min(cand, OI2[0] >> 16);
                if (__float_as_uint(dr[2]) == gvbA) cand = min(cand, OI2[1] & 0xFFFFu);
                if (__float_as_uint(dr[3]) == gvbA) cand = min(cand, OI2[1] >> 16);
                gcA = __reduce_min_sync(0xFFFFFFFFu, cand);
                float rw = __fmul_rn(sqrtf(__uint_as_float(gvbA)), 1.0001f);
                xloA = xmnA - rw; xhiA = xmxA + rw;
            }
            if (aB) {
                #pragma unroll
                for (int j = 2; j < 4; j++) {
                    unsigned long long dx2 = add2(X2[j], nqx2);
                    unsigned long long dy2 = add2(Y2[j], nqy2);
                    unsigned long long dz2 = add2(Z2[j], nqz2);
                    unsigned long long d2 = add2(add2(mul2(dx2, dx2), mul2(dy2, dy2)),
                                                 mul2(dz2, dz2));
                    float dlo, dhi;
                    unpack2(d2, dlo, dhi);
                    dr[2 * j]     = fminf(dr[2 * j],     dlo);
                    dr[2 * j + 1] = fminf(dr[2 * j + 1], dhi);
                }
                float mxg = fmaxf(fmaxf(dr[4], dr[5]), fmaxf(dr[6], dr[7]));
                gvbB = __reduce_max_sync(0xFFFFFFFFu, __float_as_uint(mxg));
                unsigned cand = 0xFFFFFFFFu;
                if (__float_as_uint(dr[4]) == gvbB) cand = OI2[2] & 0xFFFFu;
                if (__float_as_uint(dr[5]) == gvbB) cand = min(cand, OI2[2] >> 16);
                if (__float_as_uint(dr[6]) == gvbB) cand = min(cand, OI2[3] & 0xFFFFu);
                if (__float_as_uint(dr[7]) == gvbB) cand = min(cand, OI2[3] >> 16);
                gcB = __reduce_min_sync(0xFFFFFFFFu, cand);
                float rw = __fmul_rn(sqrtf(__uint_as_float(gvbB)), 1.0001f);
                xloB = xmnB - rw; xhiB = xmxB + rw;
            }
        }

        // Combine groups -> warp (value max; min index among bit-equal ties).
        unsigned wvb = max(gvbA, gvbB);
        unsigned wcand = 0xFFFFFFFFu;
        if (gvbA == wvb) wcand = gcA;
        if (gvbB == wvb) wcand = min(wcand, gcB);

        // Single-barrier block argmax over the 32 cached (wvb, wcand) pairs.
        if (lane == 0) pvi[buf * 32 + warp] = make_uint2(wvb, wcand);
        __syncthreads();
        uint2 p2 = pvi[buf * 32 + lane];                 // LDS.64
        unsigned m2 = __reduce_max_sync(0xFFFFFFFFu, p2.x);
        unsigned c2 = (p2.x == m2) ? p2.y : 0xFFFFFFFFu;
        far = __reduce_min_sync(0xFFFFFFFFu, c2);
    }
}

// Gather with channel-tiled blocks (indices preloaded to smem; coalesced
// writes; channel-plane reads get L1/L2 reuse).
#define CT 32            // channels per block
#define MT 512           // samples per block
extern "C" __global__ void __launch_bounds__(256)
gather_kernel(const float* __restrict__ feats,  // [B, C, N]
              float* __restrict__ out_feats)    // [B, M, C]
{
    __shared__ int sn[MT];
    int blk = blockIdx.x;                    // b * 32 + ct * 4 + mt
    int b   = blk >> 5;
    int ct  = (blk >> 2) & 7;                // 8 channel tiles
    int mt  = blk & 3;                       // 4 sample tiles
    int tid = threadIdx.x;

    for (int i = tid; i < MT; i += 256)
        sn[i] = g_idx[b * MM + mt * MT + i];
    __syncthreads();

    int c  = ct * CT + (tid & 31);
    int ml = tid >> 5;                       // 0..7
    const float* fp = feats + ((size_t)b * CC + c) * NN;
    float* op = out_feats + ((size_t)b * MM + mt * MT) * CC + c;

    #pragma unroll 4
    for (int mm = ml; mm < MT; mm += 8)
        op[(size_t)mm * CC] = fp[sn[mm]];
}

// Tiny kernel to keep ncu's "-s 5 -c 1" window on fps_kernel.
extern "C" __global__ void warm_kernel() {}

extern "C" void kernel_launch(void* const* d_in, const int* in_sizes, int n_in,
                              void* d_out, int out_size)
{
    const float* pts   = (const float*)d_in[0];  // [B, 3, N]
    const float* feats = (const float*)d_in[1];  // [B, C, N]
    float* out = (float*)d_out;

    cudaFuncSetAttribute(fps_kernel,
                         cudaFuncAttributeMaxDynamicSharedMemorySize, SMEM_BYTES);

    fps_kernel<<<BB, TT, SMEM_BYTES>>>(pts, out);
    warm_kernel<<<1, 1>>>();
    gather_kernel<<<BB * 32, 256>>>(feats, out + (size_t)BB * MM * 3);
}

// round 11
// speedup vs baseline: 1.0699x; 1.0699x over previous
#include <cuda_runtime.h>

// Problem constants (fixed: B=16, N=8192, C=256, num_points=2048)
#define BB   16
#define NN   8192
#define CC   256
#define MM   2048
#define TT   512           // threads per FPS block (regs cap 128 -> no spills)
#define NW   (TT / 32)     // 16 warps
#define PPT  (NN / TT)     // points per thread = 16
#define NPAIR (PPT / 2)    // f32x2 pairs per thread = 8
#define NG   4             // groups per warp (128 sorted points each)

// Scratch: selected indices, written by FPS kernel, read by gather kernel.
__device__ int g_idx[BB * MM];

// Dynamic smem layout (floats/uints, see pointers in kernel):
// sq4[NN] float4 | pvi[2*NW] uint2 | initv[NW] | initi[NW] | cent[3*NW]
// | wext[NW*NG] float2 | skx[NN] | ski[NN]
#define SMEM_BYTES (NN * 16 + 2 * NW * 8 + NW * 4 + NW * 4 + 3 * NW * 4 \
                    + NW * NG * 8 + NN * 4 + NN * 4)

// ---- packed f32x2 helpers (sm_103a) ---------------------------------------
__device__ __forceinline__ unsigned long long pack2(float lo, float hi) {
    unsigned long long r;
    asm("mov.b64 %0, {%1, %2};" : "=l"(r) : "f"(lo), "f"(hi));
    return r;
}
__device__ __forceinline__ void unpack2(unsigned long long v, float& lo, float& hi) {
    asm("mov.b64 {%0, %1}, %2;" : "=f"(lo), "=f"(hi) : "l"(v));
}
__device__ __forceinline__ unsigned long long add2(unsigned long long a, unsigned long long b) {
    unsigned long long r;
    asm("add.rn.f32x2 %0, %1, %2;" : "=l"(r) : "l"(a), "l"(b));
    return r;
}
__device__ __forceinline__ unsigned long long mul2(unsigned long long a, unsigned long long b) {
    unsigned long long r;
    asm("mul.rn.f32x2 %0, %1, %2;" : "=l"(r) : "l"(a), "l"(b));
    return r;
}
// ---------------------------------------------------------------------------

__device__ __forceinline__ float warp_sum(float x) {
    #pragma unroll
    for (int o = 16; o > 0; o >>= 1)
        x += __shfl_xor_sync(0xFFFFFFFFu, x, o);
    return x;
}
__device__ __forceinline__ float warp_min(float x) {
    #pragma unroll
    for (int o = 16; o > 0; o >>= 1)
        x = fminf(x, __shfl_xor_sync(0xFFFFFFFFu, x, o));
    return x;
}
__device__ __forceinline__ float warp_max(float x) {
    #pragma unroll
    for (int o = 16; o > 0; o >>= 1)
        x = fmaxf(x, __shfl_xor_sync(0xFFFFFFFFu, x, o));
    return x;
}

extern "C" __global__ void __launch_bounds__(TT, 1)
fps_kernel(const float* __restrict__ pts,   // [B, 3, N]
           float* __restrict__ out_pts)     // [B, M, 3]
{
    extern __shared__ unsigned char smraw[];
    float4*   sq4   = (float4*)smraw;                  // [NN] orig-indexed coords
    uint2*    pvi   = (uint2*)(smraw + NN * 16);       // [2*NW] (val,cand) bufs
    unsigned* initv = (unsigned*)(pvi + 2 * NW);       // [NW]
    unsigned* initi = initv + NW;                      // [NW]
    float*    cent  = (float*)(initi + NW);            // [3*NW]
    float2*   wext  = (float2*)(cent + 3 * NW);        // [NW*NG] (xmn, xmx)
    float*    skx   = (float*)(wext + NW * NG);        // [NN] sort keys (x)
    int*      ski   = (int*)(skx + NN);                // [NN] orig indices

    const int b    = blockIdx.x;
    const int tid  = threadIdx.x;
    const int lane = tid & 31;
    const int warp = tid >> 5;

    const float* px = pts + (size_t)b * 3 * NN;
    const float* py = px + NN;
    const float* pz = px + 2 * NN;

    // ---- load (orig layout), centroid sums, sort-key init ----
    float s1 = 0.f, s2 = 0.f, s3 = 0.f;
    #pragma unroll
    for (int k = 0; k < PPT; k++) {
        int n = tid + k * TT;               // coalesced
        float x = px[n], y = py[n], z = pz[n];
        sq4[n] = make_float4(x, y, z, 0.f);
        skx[n] = x; ski[n] = n;
        s1 += x; s2 += y; s3 += z;
    }
    s1 = warp_sum(s1); s2 = warp_sum(s2); s3 = warp_sum(s3);
    if (lane == 0) { cent[warp] = s1; cent[NW + warp] = s2; cent[2 * NW + warp] = s3; }

    // ---- bitonic sort by x (permutation-preserving; quality only affects
    //      pruning, never correctness) ----
    for (int k = 2; k <= NN; k <<= 1) {
        for (int j = k >> 1; j > 0; j >>= 1) {
            __syncthreads();
            #pragma unroll 4
            for (int t = tid; t < NN / 2; t += TT) {
                int i = 2 * t - (t & (j - 1));
                int l = i + j;
                bool up = ((i & k) == 0);
                float a = skx[i], c = skx[l];
                bool sw = up ? (a > c) : (a < c);
                if (sw) {
                    skx[i] = c; skx[l] = a;
                    int ta = ski[i]; ski[i] = ski[l]; ski[l] = ta;
                }
            }
        }
    }
    __syncthreads();

    // ---- reorder into registers: warp w owns sorted ranks [512w, 512w+512).
    //      Group g (0..3) = k in [4g, 4g+4) = 128 contiguous sorted points. ----
    unsigned long long X2[NPAIR], Y2[NPAIR], Z2[NPAIR];
    unsigned OI2[NPAIR];                    // packed orig indices (lo | hi<<16)
    float dr[PPT];
    {
        float xs[PPT], ys[PPT], zs[PPT];
        unsigned oi[PPT];
        const int base = warp * (32 * PPT) + lane;
        #pragma unroll
        for (int k = 0; k < PPT; k++) {
            int r = base + 32 * k;
            int idx = ski[r];
            float4 p = sq4[idx];
            xs[k] = p.x; ys[k] = p.y; zs[k] = p.z;
            oi[k] = (unsigned)idx;
            dr[k] = 1e10f;
        }
        #pragma unroll
        for (int j = 0; j < NPAIR; j++) {
            X2[j] = pack2(xs[2 * j], xs[2 * j + 1]);
            Y2[j] = pack2(ys[2 * j], ys[2 * j + 1]);
            Z2[j] = pack2(zs[2 * j], zs[2 * j + 1]);
            OI2[j] = oi[2 * j] | (oi[2 * j + 1] << 16);
        }
        // Per-group x-extents (from points actually held) -> smem (rare reads).
        #pragma unroll
        for (int g = 0; g < NG; g++) {
            float mn = fminf(fminf(xs[4 * g], xs[4 * g + 1]),
                             fminf(xs[4 * g + 2], xs[4 * g + 3]));
            float mx = fmaxf(fmaxf(xs[4 * g], xs[4 * g + 1]),
                             fmaxf(xs[4 * g + 2], xs[4 * g + 3]));
            mn = warp_min(mn); mx = warp_max(mx);
            if (lane == 0) wext[warp * NG + g] = make_float2(mn, mx);
        }

        // Centroid finalize (16 valid partials).
        float cx = warp_sum(lane < NW ? cent[lane] : 0.f)          * (1.0f / NN);
        float cy = warp_sum(lane < NW ? cent[NW + lane] : 0.f)     * (1.0f / NN);
        float cz = warp_sum(lane < NW ? cent[2 * NW + lane] : 0.f) * (1.0f / NN);

        // d0 = ||p - centroid||^2, initial farthest (exact plain form; orig-idx
        // tie-break since held points are no longer index-ordered).
        float best = -1.0f; unsigned bi = 0xFFFFFFFFu;
        #pragma unroll
        for (int k = 0; k < PPT; k++) {
            float dx = xs[k] - cx, dy = ys[k] - cy, dz = zs[k] - cz;
            float d = __fadd_rn(__fadd_rn(__fmul_rn(dx, dx), __fmul_rn(dy, dy)),
                                __fmul_rn(dz, dz));
            if (d > best)            { best = d; bi = oi[k]; }
            else if (d == best && oi[k] < bi) bi = oi[k];
        }
        unsigned vb = __float_as_uint(best);
        unsigned m1 = __reduce_max_sync(0xFFFFFFFFu, vb);
        unsigned c1 = (vb == m1) ? bi : 0xFFFFFFFFu;
        unsigned i1 = __reduce_min_sync(0xFFFFFFFFu, c1);
        if (lane == 0) { initv[warp] = m1; initi[warp] = i1; }
    }
    __syncthreads();
    unsigned far;
    {
        unsigned v2 = (lane < NW) ? initv[lane] : 0u;
        unsigned i2 = (lane < NW) ? initi[lane] : 0xFFFFFFFFu;
        unsigned m2 = __reduce_max_sync(0xFFFFFFFFu, v2);
        unsigned c2 = (v2 == m2) ? i2 : 0xFFFFFFFFu;
        far = __reduce_min_sync(0xFFFFFFFFu, c2);
    }

    float* outp = out_pts + (size_t)b * MM * 3;
    int*   idxp = g_idx + b * MM;

    // Per-group cached state (exact while skipped): max-dr bits, min orig idx
    // among bit-equal ties, active interval [xlo, xhi]. First iteration: all
    // groups active (intervals infinite), which initializes everything.
    unsigned gvb[NG], gc[NG];
    float xlo[NG], xhi[NG];
    #pragma unroll
    for (int g = 0; g < NG; g++) {
        gvb[g] = __float_as_uint(1e10f); gc[g] = 0xFFFFFFFFu;
        xlo[g] = -1e30f; xhi[g] = 1e30f;
    }
    unsigned wvb = 0u, wcand = 0xFFFFFFFFu;   // combined cache (set on 1st iter)

    for (int m = 0; m < MM; m++) {
        const int buf = m & 1;
        // Broadcast the selected point (one LDS.128, orig-indexed table).
        float4 q = sq4[far];
        if (tid == 0) {
            idxp[m] = (int)far;
            outp[m * 3 + 0] = q.x;
            outp[m * 3 + 1] = q.y;
            outp[m * 3 + 2] = q.z;
        }

        // Interval prune per group: q.x outside [xmn-rw, xmx+rw] with
        // rw = sqrt(gmax)*1.0001 ==> dx^2 alone exceeds gmax by >1e-4 rel
        // (dwarfing all <= ~6 ulp rounding) ==> every fminf in the group is a
        // bit-level no-op; all caches stay exact.
        bool act[NG]; bool any = false;
        #pragma unroll
        for (int g = 0; g < NG; g++) {
            act[g] = (q.x >= xlo[g]) && (q.x <= xhi[g]);
            any |= act[g];
        }

        if (any) {
            unsigned long long nqx2 = pack2(-q.x, -q.x);
            unsigned long long nqy2 = pack2(-q.y, -q.y);
            unsigned long long nqz2 = pack2(-q.z, -q.z);
            #pragma unroll
            for (int g = 0; g < NG; g++) {
                if (act[g]) {
                    #pragma unroll
                    for (int j = 2 * g; j < 2 * g + 2; j++) {
                        unsigned long long dx2 = add2(X2[j], nqx2);
                        unsigned long long dy2 = add2(Y2[j], nqy2);
                        unsigned long long dz2 = add2(Z2[j], nqz2);
                        unsigned long long d2 = add2(add2(mul2(dx2, dx2),
                                                          mul2(dy2, dy2)),
                                                     mul2(dz2, dz2));
                        float dlo, dhi;
                        unpack2(d2, dlo, dhi);
                        dr[2 * j]     = fminf(dr[2 * j],     dlo);
                        dr[2 * j + 1] = fminf(dr[2 * j + 1], dhi);
                    }
                    float mxg = fmaxf(fmaxf(dr[4 * g], dr[4 * g + 1]),
                                      fmaxf(dr[4 * g + 2], dr[4 * g + 3]));
                    gvb[g] = __reduce_max_sync(0xFFFFFFFFu, __float_as_uint(mxg));
                    unsigned cand = 0xFFFFFFFFu;
                    if (__float_as_uint(dr[4 * g])     == gvb[g])
                        cand = OI2[2 * g] & 0xFFFFu;
                    if (__float_as_uint(dr[4 * g + 1]) == gvb[g])
                        cand = min(cand, OI2[2 * g] >> 16);
                    if (__float_as_uint(dr[4 * g + 2]) == gvb[g])
                        cand = min(cand, OI2[2 * g + 1] & 0xFFFFu);
                    if (__float_as_uint(dr[4 * g + 3]) == gvb[g])
                        cand = min(cand, OI2[2 * g + 1] >> 16);
                    gc[g] = __reduce_min_sync(0xFFFFFFFFu, cand);
                    // New active interval (group extent from smem; rare path).
                    float2 e = wext[warp * NG + g];       // warp-uniform LDS
                    float rw = __fmul_rn(__fsqrt_rn(__uint_as_float(gvb[g])),
                                         1.0001f);
                    xlo[g] = e.x - rw; xhi[g] = e.y + rw;
                }
            }
            // Recombine the warp-level cache (only when something changed).
            wvb = max(max(gvb[0], gvb[1]), max(gvb[2], gvb[3]));
            wcand = 0xFFFFFFFFu;
            #pragma unroll
            for (int g = 0; g < NG; g++)
                if (gvb[g] == wvb) wcand = min(wcand, gc[g]);
        }

        // Single-barrier block argmax over the NW cached (wvb, wcand) pairs.
        if (lane == 0) pvi[buf * NW + warp] = make_uint2(wvb, wcand);
        __syncthreads();
        uint2 p2 = pvi[buf * NW + (lane & (NW - 1))];    // dupes harmless
        unsigned m2 = __reduce_max_sync(0xFFFFFFFFu, p2.x);
        unsigned c2 = (p2.x == m2) ? p2.y : 0xFFFFFFFFu;
        far = __reduce_min_sync(0xFFFFFFFFu, c2);
    }
}

// Gather with channel-tiled blocks (indices preloaded to smem; coalesced
// writes; channel-plane reads get L1/L2 reuse).
#define CT 32            // channels per block
#define MT 512           // samples per block
extern "C" __global__ void __launch_bounds__(256)
gather_kernel(const float* __restrict__ feats,  // [B, C, N]
              float* __restrict__ out_feats)    // [B, M, C]
{
    __shared__ int sn[MT];
    int blk = blockIdx.x;                    // b * 32 + ct * 4 + mt
    int b   = blk >> 5;
    int ct  = (blk >> 2) & 7;                // 8 channel tiles
    int mt  = blk & 3;                       // 4 sample tiles
    int tid = threadIdx.x;

    for (int i = tid; i < MT; i += 256)
        sn[i] = g_idx[b * MM + mt * MT + i];
    __syncthreads();

    int c  = ct * CT + (tid & 31);
    int ml = tid >> 5;                       // 0..7
    const float* fp = feats + ((size_t)b * CC + c) * NN;
    float* op = out_feats + ((size_t)b * MM + mt * MT) * CC + c;

    #pragma unroll 4
    for (int mm = ml; mm < MT; mm += 8)
        op[(size_t)mm * CC] = fp[sn[mm]];
}

// Tiny kernel to keep ncu's "-s 5 -c 1" window on fps_kernel.
extern "C" __global__ void warm_kernel() {}

extern "C" void kernel_launch(void* const* d_in, const int* in_sizes, int n_in,
                              void* d_out, int out_size)
{
    const float* pts   = (const float*)d_in[0];  // [B, 3, N]
    const float* feats = (const float*)d_in[1];  // [B, C, N]
    float* out = (float*)d_out;

    cudaFuncSetAttribute(fps_kernel,
                         cudaFuncAttributeMaxDynamicSharedMemorySize, SMEM_BYTES);

    fps_kernel<<<BB, TT, SMEM_BYTES>>>(pts, out);
    warm_kernel<<<1, 1>>>();
    gather_kernel<<<BB * 32, 256>>>(feats, out + (size_t)BB * MM * 3);
}